// round 2
// baseline (speedup 1.0000x reference)
#include <cuda_runtime.h>
#include <cuda_bf16.h>

#define SH_C0 0.28209479177387814f
#define SH_C1 0.4886025119029199f

__device__ __constant__ float SH_C2d[5] = {1.0925484305920792f, -1.0925484305920792f, 0.31539156525252005f, -1.0925484305920792f, 0.5462742152960396f};
__device__ __constant__ float SH_C3d[7] = {-0.5900435899266435f, 2.890611442640554f, -0.4570457994644658f, 0.3731763325901154f, -0.4570457994644658f, 1.445305721320277f, -0.5900435899266435f};

#define TILE 256

__global__ void __launch_bounds__(TILE, 4)
gsh_kernel(const float* __restrict__ means,
           const float* __restrict__ fdc,
           const float* __restrict__ frest,
           const float* __restrict__ opac,
           const float* __restrict__ c2w,
           const int*   __restrict__ mask,
           const int*   __restrict__ step,
           float* __restrict__ out_rgb,
           float* __restrict__ out_opac,
           int M)
{
    __shared__ int   s_idx[TILE];
    __shared__ float s_feat[TILE * 45];   // frest rows
    __shared__ float s_mean[TILE * 3];
    __shared__ float s_fdc[TILE * 3];
    __shared__ float s_op[TILE];

    const int tid  = threadIdx.x;
    const int base = blockIdx.x * TILE;
    const int cnt  = min(TILE, M - base);   // valid points in this tile

    // --- stage indices ---
    if (tid < cnt) s_idx[tid] = __ldg(mask + base + tid);
    __syncthreads();

    // --- staged gather: flat loops, consecutive lanes read consecutive
    //     floats of the SAME scattered row -> 1-2 lines per warp LDG ---
    // frest: cnt * 45 floats
    {
        const int total = cnt * 45;
        for (int f = tid; f < total; f += TILE) {
            int p = f / 45;
            int j = f - p * 45;
            s_feat[f] = __ldg(frest + 45ll * s_idx[p] + j);
        }
    }
    // means + fdc: cnt * 3 each
    {
        const int total = cnt * 3;
        for (int f = tid; f < total; f += TILE) {
            int p = f / 3;
            int j = f - p * 3;
            long idx = s_idx[p];
            s_mean[f] = __ldg(means + 3ll * idx + j);
            s_fdc[f]  = __ldg(fdc   + 3ll * idx + j);
        }
    }
    // opacity
    if (tid < cnt) s_op[tid] = __ldg(opac + s_idx[tid]);
    __syncthreads();

    if (tid >= cnt) return;

    const int i = base + tid;

    const float camx = __ldg(c2w + 3);
    const float camy = __ldg(c2w + 7);
    const float camz = __ldg(c2w + 11);

    float dx = s_mean[tid * 3 + 0] - camx;
    float dy = s_mean[tid * 3 + 1] - camy;
    float dz = s_mean[tid * 3 + 2] - camz;
    float inv = rsqrtf(dx * dx + dy * dy + dz * dz);
    float x = dx * inv, y = dy * inv, z = dz * inv;

    int n = min(__ldg(step) / 1000, 3);

    float sh[16];
    sh[0] = SH_C0;
    sh[1] = -SH_C1 * y;
    sh[2] =  SH_C1 * z;
    sh[3] = -SH_C1 * x;
    float xx = x * x, yy = y * y, zz = z * z;
    float xy = x * y, yz = y * z, xz = x * z;
    sh[4] = SH_C2d[0] * xy;
    sh[5] = SH_C2d[1] * yz;
    sh[6] = SH_C2d[2] * (2.0f * zz - xx - yy);
    sh[7] = SH_C2d[3] * xz;
    sh[8] = SH_C2d[4] * (xx - yy);
    sh[9]  = SH_C3d[0] * y * (3.0f * xx - yy);
    sh[10] = SH_C3d[1] * xy * z;
    sh[11] = SH_C3d[2] * y * (4.0f * zz - xx - yy);
    sh[12] = SH_C3d[3] * z * (2.0f * zz - 3.0f * xx - 3.0f * yy);
    sh[13] = SH_C3d[4] * x * (4.0f * zz - xx - yy);
    sh[14] = SH_C3d[5] * z * (xx - yy);
    sh[15] = SH_C3d[6] * x * (xx - 3.0f * yy);

    const int k = (n + 1) * (n + 1);

    float r = sh[0] * s_fdc[tid * 3 + 0];
    float g = sh[0] * s_fdc[tid * 3 + 1];
    float b = sh[0] * s_fdc[tid * 3 + 2];

    const float* fr = &s_feat[tid * 45];
#pragma unroll
    for (int j = 1; j < 16; ++j) {
        if (j < k) {
            float c = sh[j];
            r += c * fr[(j - 1) * 3 + 0];
            g += c * fr[(j - 1) * 3 + 1];
            b += c * fr[(j - 1) * 3 + 2];
        }
    }

    r = fmaxf(r + 0.5f, 0.0f);
    g = fmaxf(g + 0.5f, 0.0f);
    b = fmaxf(b + 0.5f, 0.0f);

    out_rgb[3ll * i + 0] = r;
    out_rgb[3ll * i + 1] = g;
    out_rgb[3ll * i + 2] = b;
    out_opac[i] = s_op[tid];
}

extern "C" void kernel_launch(void* const* d_in, const int* in_sizes, int n_in,
                              void* d_out, int out_size)
{
    const float* means = (const float*)d_in[0];
    const float* fdc   = (const float*)d_in[1];
    const float* frest = (const float*)d_in[2];
    const float* opac  = (const float*)d_in[3];
    const float* c2w   = (const float*)d_in[4];
    const int*   mask  = (const int*)d_in[5];
    const int*   step  = (const int*)d_in[6];

    int M = in_sizes[5];
    float* out_rgb  = (float*)d_out;
    float* out_opac = (float*)d_out + 3ll * M;

    int blocks = (M + TILE - 1) / TILE;
    gsh_kernel<<<blocks, TILE>>>(means, fdc, frest, opac, c2w, mask, step,
                                 out_rgb, out_opac, M);
}

// round 6
// speedup vs baseline: 1.5346x; 1.5346x over previous
#include <cuda_runtime.h>
#include <cuda_bf16.h>

#define SH_C0 0.28209479177387814f
#define SH_C1 0.4886025119029199f

__device__ __constant__ float SH_C2d[5] = {1.0925484305920792f, -1.0925484305920792f, 0.31539156525252005f, -1.0925484305920792f, 0.5462742152960396f};
__device__ __constant__ float SH_C3d[7] = {-0.5900435899266435f, 2.890611442640554f, -0.4570457994644658f, 0.3731763325901154f, -0.4570457994644658f, 1.445305721320277f, -0.5900435899266435f};

// One thread per point, software-pipelined gather:
//   batch0: means/fdc/opac + deg1 features (16 LDGs)
//   batch1: deg2 features (15 LDGs)      -- issued before batch0 is consumed
//   batch2: deg3 features (21 LDGs)      -- issued before batch1 is consumed
// Peak ~31-36 independent loads in flight per thread at moderate register
// pressure, hiding ~577-cycle DRAM latency without tanking occupancy.
__global__ void __launch_bounds__(128)
gsh_kernel(const float* __restrict__ means,
           const float* __restrict__ fdc,
           const float* __restrict__ frest,
           const float* __restrict__ opac,
           const float* __restrict__ c2w,
           const int*   __restrict__ mask,
           const int*   __restrict__ step,
           float* __restrict__ out_rgb,
           float* __restrict__ out_opac,
           int M)
{
    int i = blockIdx.x * blockDim.x + threadIdx.x;
    if (i >= M) return;

    const int idx = __ldg(mask + i);
    const float* __restrict__ fr = frest + 45ll * idx;

    // ---- batch 0: geometry + dc + opacity + degree-1 features ----
    float mx = __ldg(means + 3ll * idx + 0);
    float my = __ldg(means + 3ll * idx + 1);
    float mz = __ldg(means + 3ll * idx + 2);
    float d0 = __ldg(fdc + 3ll * idx + 0);
    float d1 = __ldg(fdc + 3ll * idx + 1);
    float d2 = __ldg(fdc + 3ll * idx + 2);
    float op = __ldg(opac + idx);
    float f1[9];
#pragma unroll
    for (int j = 0; j < 9; ++j) f1[j] = __ldg(fr + j);

    // ---- batch 1: degree-2 features (issued before any consumption) ----
    float f2[15];
#pragma unroll
    for (int j = 0; j < 15; ++j) f2[j] = __ldg(fr + 9 + j);

    const float camx = __ldg(c2w + 3);
    const float camy = __ldg(c2w + 7);
    const float camz = __ldg(c2w + 11);
    const int n = min(__ldg(step) / 1000, 3);

    // ---- compute direction + basis (overlaps batch-1 flight) ----
    float dx = mx - camx;
    float dy = my - camy;
    float dz = mz - camz;
    float inv = rsqrtf(dx * dx + dy * dy + dz * dz);
    float x = dx * inv, y = dy * inv, z = dz * inv;

    float xx = x * x, yy = y * y, zz = z * z;
    float xy = x * y, yz = y * z, xz = x * z;

    float r = SH_C0 * d0;
    float g = SH_C0 * d1;
    float b = SH_C0 * d2;

    // ---- consume degree 1 ----
    if (n >= 1) {
        float s1 = -SH_C1 * y;
        float s2 =  SH_C1 * z;
        float s3 = -SH_C1 * x;
        r += s1 * f1[0] + s2 * f1[3] + s3 * f1[6];
        g += s1 * f1[1] + s2 * f1[4] + s3 * f1[7];
        b += s1 * f1[2] + s2 * f1[5] + s3 * f1[8];
    }

    // ---- batch 2: degree-3 features (issued before batch-1 consumed) ----
    float f3[21];
#pragma unroll
    for (int j = 0; j < 21; ++j) f3[j] = __ldg(fr + 24 + j);

    // ---- consume degree 2 ----
    if (n >= 2) {
        float s4 = SH_C2d[0] * xy;
        float s5 = SH_C2d[1] * yz;
        float s6 = SH_C2d[2] * (2.0f * zz - xx - yy);
        float s7 = SH_C2d[3] * xz;
        float s8 = SH_C2d[4] * (xx - yy);
        r += s4 * f2[0] + s5 * f2[3] + s6 * f2[6]  + s7 * f2[9]  + s8 * f2[12];
        g += s4 * f2[1] + s5 * f2[4] + s6 * f2[7]  + s7 * f2[10] + s8 * f2[13];
        b += s4 * f2[2] + s5 * f2[5] + s6 * f2[8]  + s7 * f2[11] + s8 * f2[14];
    }

    // ---- consume degree 3 ----
    if (n >= 3) {
        float s9  = SH_C3d[0] * y * (3.0f * xx - yy);
        float s10 = SH_C3d[1] * xy * z;
        float s11 = SH_C3d[2] * y * (4.0f * zz - xx - yy);
        float s12 = SH_C3d[3] * z * (2.0f * zz - 3.0f * xx - 3.0f * yy);
        float s13 = SH_C3d[4] * x * (4.0f * zz - xx - yy);
        float s14 = SH_C3d[5] * z * (xx - yy);
        float s15 = SH_C3d[6] * x * (xx - 3.0f * yy);
        r += s9 * f3[0] + s10 * f3[3] + s11 * f3[6]  + s12 * f3[9];
        g += s9 * f3[1] + s10 * f3[4] + s11 * f3[7]  + s12 * f3[10];
        b += s9 * f3[2] + s10 * f3[5] + s11 * f3[8]  + s12 * f3[11];
        r += s13 * f3[12] + s14 * f3[15] + s15 * f3[18];
        g += s13 * f3[13] + s14 * f3[16] + s15 * f3[19];
        b += s13 * f3[14] + s14 * f3[17] + s15 * f3[20];
    }

    r = fmaxf(r + 0.5f, 0.0f);
    g = fmaxf(g + 0.5f, 0.0f);
    b = fmaxf(b + 0.5f, 0.0f);

    out_rgb[3ll * i + 0] = r;
    out_rgb[3ll * i + 1] = g;
    out_rgb[3ll * i + 2] = b;
    out_opac[i] = op;
}

extern "C" void kernel_launch(void* const* d_in, const int* in_sizes, int n_in,
                              void* d_out, int out_size)
{
    const float* means = (const float*)d_in[0];
    const float* fdc   = (const float*)d_in[1];
    const float* frest = (const float*)d_in[2];
    const float* opac  = (const float*)d_in[3];
    const float* c2w   = (const float*)d_in[4];
    const int*   mask  = (const int*)d_in[5];
    const int*   step  = (const int*)d_in[6];

    int M = in_sizes[5];
    float* out_rgb  = (float*)d_out;
    float* out_opac = (float*)d_out + 3ll * M;

    int threads = 128;
    int blocks = (M + threads - 1) / threads;
    gsh_kernel<<<blocks, threads>>>(means, fdc, frest, opac, c2w, mask, step,
                                    out_rgb, out_opac, M);
}

// round 9
// speedup vs baseline: 1.8221x; 1.1873x over previous
#include <cuda_runtime.h>
#include <cuda_bf16.h>

#define SH_C0 0.28209479177387814f
#define SH_C1 0.4886025119029199f

__device__ __constant__ float SH_C2d[5] = {1.0925484305920792f, -1.0925484305920792f, 0.31539156525252005f, -1.0925484305920792f, 0.5462742152960396f};
__device__ __constant__ float SH_C3d[7] = {-0.5900435899266435f, 2.890611442640554f, -0.4570457994644658f, 0.3731763325901154f, -0.4570457994644658f, 1.445305721320277f, -0.5900435899266435f};

// One thread per point. The 45-float frest row (180B, 4B-aligned) is gathered
// via 11 aligned LDG.128 from (base & ~15) — always in-bounds for the row —
// plus 4 scalar tail loads for elements 41..44. A predicated register shift
// by the 0..3-word misalignment realigns the window. The shift consumes the
// whole window at once, so ptxas must issue all 11 wide loads before any
// consumption: forced MLP >= 11 LDG.128/thread, ~2.3x fewer L1tex wavefronts
// than a 45-scalar gather.
__global__ void __launch_bounds__(256)
gsh_kernel(const float* __restrict__ means,
           const float* __restrict__ fdc,
           const float* __restrict__ frest,
           const float* __restrict__ opac,
           const float* __restrict__ c2w,
           const int*   __restrict__ mask,
           const int*   __restrict__ step,
           float* __restrict__ out_rgb,
           float* __restrict__ out_opac,
           int M)
{
    const int i = blockIdx.x * blockDim.x + threadIdx.x;
    if (i >= M) return;

    const long long idx = (long long)__ldg(mask + i);

    // ---- frest windowed vector gather ----
    const long long base_bytes = 180ll * idx;            // row start, 4B aligned
    const long long albase     = base_bytes & ~15ll;     // 16B aligned window
    const int s = (int)((base_bytes - albase) >> 2);     // word shift 0..3
    const float4* __restrict__ vp = (const float4*)((const char*)frest + albase);

    float4 v0 = __ldg(vp + 0);
    float4 v1 = __ldg(vp + 1);
    float4 v2 = __ldg(vp + 2);
    float4 v3 = __ldg(vp + 3);
    float4 v4 = __ldg(vp + 4);
    float4 v5 = __ldg(vp + 5);
    float4 v6 = __ldg(vp + 6);
    float4 v7 = __ldg(vp + 7);
    float4 v8 = __ldg(vp + 8);
    float4 v9 = __ldg(vp + 9);
    float4 va = __ldg(vp + 10);

    // tail: row elements 41..44 (bytes base+164 .. base+179, in-bounds)
    const float* __restrict__ frow = frest + 45ll * idx;
    const float t41 = __ldg(frow + 41);
    const float t42 = __ldg(frow + 42);
    const float t43 = __ldg(frow + 43);
    const float t44 = __ldg(frow + 44);

    // geometry / dc / opacity (issued while the vectors are in flight)
    const float mx = __ldg(means + 3ll * idx + 0);
    const float my = __ldg(means + 3ll * idx + 1);
    const float mz = __ldg(means + 3ll * idx + 2);
    const float d0 = __ldg(fdc + 3ll * idx + 0);
    const float d1 = __ldg(fdc + 3ll * idx + 1);
    const float d2 = __ldg(fdc + 3ll * idx + 2);
    const float op = __ldg(opac + idx);

    const float camx = __ldg(c2w + 3);
    const float camy = __ldg(c2w + 7);
    const float camz = __ldg(c2w + 11);
    const int n = min(__ldg(step) / 1000, 3);

    // ---- unpack window into w[0..43] ----
    float w[44];
    w[0]=v0.x; w[1]=v0.y; w[2]=v0.z; w[3]=v0.w;
    w[4]=v1.x; w[5]=v1.y; w[6]=v1.z; w[7]=v1.w;
    w[8]=v2.x; w[9]=v2.y; w[10]=v2.z; w[11]=v2.w;
    w[12]=v3.x; w[13]=v3.y; w[14]=v3.z; w[15]=v3.w;
    w[16]=v4.x; w[17]=v4.y; w[18]=v4.z; w[19]=v4.w;
    w[20]=v5.x; w[21]=v5.y; w[22]=v5.z; w[23]=v5.w;
    w[24]=v6.x; w[25]=v6.y; w[26]=v6.z; w[27]=v6.w;
    w[28]=v7.x; w[29]=v7.y; w[30]=v7.z; w[31]=v7.w;
    w[32]=v8.x; w[33]=v8.y; w[34]=v8.z; w[35]=v8.w;
    w[36]=v9.x; w[37]=v9.y; w[38]=v9.z; w[39]=v9.w;
    w[40]=va.x; w[41]=va.y; w[42]=va.z; w[43]=va.w;

    // ---- realign: after this, w[j] == frest row element j (j <= 40) ----
    if (s & 2) {
#pragma unroll
        for (int k = 0; k < 42; ++k) w[k] = w[k + 2];
    }
    if (s & 1) {
#pragma unroll
        for (int k = 0; k < 41; ++k) w[k] = w[k + 1];
    }

    // ---- compute ----
    const float dx = mx - camx;
    const float dy = my - camy;
    const float dz = mz - camz;
    const float inv = rsqrtf(dx * dx + dy * dy + dz * dz);
    const float x = dx * inv, y = dy * inv, z = dz * inv;

    const float xx = x * x, yy = y * y, zz = z * z;
    const float xy = x * y, yz = y * z, xz = x * z;

    float r = SH_C0 * d0;
    float g = SH_C0 * d1;
    float b = SH_C0 * d2;

    if (n >= 1) {
        const float s1 = -SH_C1 * y;
        const float s2 =  SH_C1 * z;
        const float s3 = -SH_C1 * x;
        r += s1 * w[0] + s2 * w[3] + s3 * w[6];
        g += s1 * w[1] + s2 * w[4] + s3 * w[7];
        b += s1 * w[2] + s2 * w[5] + s3 * w[8];
    }
    if (n >= 2) {
        const float s4 = SH_C2d[0] * xy;
        const float s5 = SH_C2d[1] * yz;
        const float s6 = SH_C2d[2] * (2.0f * zz - xx - yy);
        const float s7 = SH_C2d[3] * xz;
        const float s8 = SH_C2d[4] * (xx - yy);
        r += s4 * w[9]  + s5 * w[12] + s6 * w[15] + s7 * w[18] + s8 * w[21];
        g += s4 * w[10] + s5 * w[13] + s6 * w[16] + s7 * w[19] + s8 * w[22];
        b += s4 * w[11] + s5 * w[14] + s6 * w[17] + s7 * w[20] + s8 * w[23];
    }
    if (n >= 3) {
        const float s9  = SH_C3d[0] * y * (3.0f * xx - yy);
        const float s10 = SH_C3d[1] * xy * z;
        const float s11 = SH_C3d[2] * y * (4.0f * zz - xx - yy);
        const float s12 = SH_C3d[3] * z * (2.0f * zz - 3.0f * xx - 3.0f * yy);
        const float s13 = SH_C3d[4] * x * (4.0f * zz - xx - yy);
        const float s14 = SH_C3d[5] * z * (xx - yy);
        const float s15 = SH_C3d[6] * x * (xx - 3.0f * yy);
        r += s9 * w[24] + s10 * w[27] + s11 * w[30] + s12 * w[33];
        g += s9 * w[25] + s10 * w[28] + s11 * w[31] + s12 * w[34];
        b += s9 * w[26] + s10 * w[29] + s11 * w[32] + s12 * w[35];
        r += s13 * w[36] + s14 * w[39] + s15 * t42;
        g += s13 * w[37] + s14 * w[40] + s15 * t43;
        b += s13 * w[38] + s14 * t41   + s15 * t44;
    }

    r = fmaxf(r + 0.5f, 0.0f);
    g = fmaxf(g + 0.5f, 0.0f);
    b = fmaxf(b + 0.5f, 0.0f);

    out_rgb[3ll * i + 0] = r;
    out_rgb[3ll * i + 1] = g;
    out_rgb[3ll * i + 2] = b;
    out_opac[i] = op;
}

extern "C" void kernel_launch(void* const* d_in, const int* in_sizes, int n_in,
                              void* d_out, int out_size)
{
    const float* means = (const float*)d_in[0];
    const float* fdc   = (const float*)d_in[1];
    const float* frest = (const float*)d_in[2];
    const float* opac  = (const float*)d_in[3];
    const float* c2w   = (const float*)d_in[4];
    const int*   mask  = (const int*)d_in[5];
    const int*   step  = (const int*)d_in[6];

    int M = in_sizes[5];
    float* out_rgb  = (float*)d_out;
    float* out_opac = (float*)d_out + 3ll * M;

    int threads = 256;
    int blocks = (M + threads - 1) / threads;
    gsh_kernel<<<blocks, threads>>>(means, fdc, frest, opac, c2w, mask, step,
                                    out_rgb, out_opac, M);
}

// round 13
// speedup vs baseline: 2.1758x; 1.1941x over previous
#include <cuda_runtime.h>
#include <cuda_bf16.h>

#define SH_C0 0.28209479177387814f
#define SH_C1 0.4886025119029199f

__device__ __constant__ float SH_C2d[5] = {1.0925484305920792f, -1.0925484305920792f, 0.31539156525252005f, -1.0925484305920792f, 0.5462742152960396f};
__device__ __constant__ float SH_C3d[7] = {-0.5900435899266435f, 2.890611442640554f, -0.4570457994644658f, 0.3731763325901154f, -0.4570457994644658f, 1.445305721320277f, -0.5900435899266435f};

// Gang-of-2: two adjacent lanes per point.
//   lane q=0: window float4s 0..6  (words 0..27)  -> elements 0..23 (deg0..2) + fdc + opac
//   lane q=1: window float4s 6..11 (words 24..47) -> elements 24..44 (deg3 exactly)
// The s-word realign shift consumes the whole per-lane window, forcing all
// wide loads to issue before consumption (MLP), at ~half the register cost of
// the one-thread-per-point version -> ~2x occupancy. Lane pairs hit adjacent
// lines -> fewer L1tex wavefronts per point. Partials reduced via shfl_xor.
__global__ void __launch_bounds__(256)
gsh_kernel(const float* __restrict__ means,
           const float* __restrict__ fdc,
           const float* __restrict__ frest,
           const float* __restrict__ opac,
           const float* __restrict__ c2w,
           const int*   __restrict__ mask,
           const int*   __restrict__ step,
           float* __restrict__ out_rgb,
           float* __restrict__ out_opac,
           int M)
{
    const int t = blockIdx.x * blockDim.x + threadIdx.x;
    const int p = t >> 1;            // point index
    const int q = t & 1;             // half: 0 = deg0..2, 1 = deg3
    if (p >= M) return;

    const long long idx = (long long)__ldg(mask + p);

    // window geometry (s = idx mod 4, uniform within the gang)
    const long long base_bytes = 180ll * idx;
    const long long albase     = base_bytes & ~15ll;
    const int s = (int)((base_bytes - albase) >> 2);

    // lane's sub-window start: q==0 -> albase, q==1 -> albase+96 (word 24)
    const float4* __restrict__ vp =
        (const float4*)((const char*)frest + albase + (q ? 96 : 0));

    // 6 unconditional wide loads + 1 predicated (lane0 only needs the 7th)
    float4 v0 = __ldg(vp + 0);
    float4 v1 = __ldg(vp + 1);
    float4 v2 = __ldg(vp + 2);
    float4 v3 = __ldg(vp + 3);
    float4 v4 = __ldg(vp + 4);
    float4 v5 = __ldg(vp + 5);
    float4 v6 = make_float4(0.f, 0.f, 0.f, 0.f);
    if (q == 0) v6 = __ldg(vp + 6);

    // geometry (both lanes need direction), dc/opac (lane0 only, predicated)
    const float mx = __ldg(means + 3ll * idx + 0);
    const float my = __ldg(means + 3ll * idx + 1);
    const float mz = __ldg(means + 3ll * idx + 2);
    float d0 = 0.f, d1 = 0.f, d2 = 0.f, op = 0.f;
    if (q == 0) {
        d0 = __ldg(fdc + 3ll * idx + 0);
        d1 = __ldg(fdc + 3ll * idx + 1);
        d2 = __ldg(fdc + 3ll * idx + 2);
        op = __ldg(opac + idx);
    }

    const float camx = __ldg(c2w + 3);
    const float camy = __ldg(c2w + 7);
    const float camz = __ldg(c2w + 11);
    const int n = min(__ldg(step) / 1000, 3);

    // unpack lane window (28 words; lane1's top 4 are dead)
    float u[28];
    u[0]=v0.x;  u[1]=v0.y;  u[2]=v0.z;  u[3]=v0.w;
    u[4]=v1.x;  u[5]=v1.y;  u[6]=v1.z;  u[7]=v1.w;
    u[8]=v2.x;  u[9]=v2.y;  u[10]=v2.z; u[11]=v2.w;
    u[12]=v3.x; u[13]=v3.y; u[14]=v3.z; u[15]=v3.w;
    u[16]=v4.x; u[17]=v4.y; u[18]=v4.z; u[19]=v4.w;
    u[20]=v5.x; u[21]=v5.y; u[22]=v5.z; u[23]=v5.w;
    u[24]=v6.x; u[25]=v6.y; u[26]=v6.z; u[27]=v6.w;

    // realign by s words: afterwards u[k] == row element (k + 24*q) for the
    // k range each lane consumes (lane0: k<=23, lane1: k<=20)
    if (s & 2) {
#pragma unroll
        for (int k = 0; k < 26; ++k) u[k] = u[k + 2];
    }
    if (s & 1) {
#pragma unroll
        for (int k = 0; k < 25; ++k) u[k] = u[k + 1];
    }

    // direction + shared squares
    const float dx = mx - camx;
    const float dy = my - camy;
    const float dz = mz - camz;
    const float inv = rsqrtf(dx * dx + dy * dy + dz * dz);
    const float x = dx * inv, y = dy * inv, z = dz * inv;
    const float xx = x * x, yy = y * y, zz = z * z;

    float r = 0.f, g = 0.f, b = 0.f;

    if (q == 0) {
        r = SH_C0 * d0;
        g = SH_C0 * d1;
        b = SH_C0 * d2;
        if (n >= 1) {
            const float s1 = -SH_C1 * y;
            const float s2 =  SH_C1 * z;
            const float s3 = -SH_C1 * x;
            r += s1 * u[0] + s2 * u[3] + s3 * u[6];
            g += s1 * u[1] + s2 * u[4] + s3 * u[7];
            b += s1 * u[2] + s2 * u[5] + s3 * u[8];
        }
        if (n >= 2) {
            const float s4 = SH_C2d[0] * (x * y);
            const float s5 = SH_C2d[1] * (y * z);
            const float s6 = SH_C2d[2] * (2.0f * zz - xx - yy);
            const float s7 = SH_C2d[3] * (x * z);
            const float s8 = SH_C2d[4] * (xx - yy);
            r += s4 * u[9]  + s5 * u[12] + s6 * u[15] + s7 * u[18] + s8 * u[21];
            g += s4 * u[10] + s5 * u[13] + s6 * u[16] + s7 * u[19] + s8 * u[22];
            b += s4 * u[11] + s5 * u[14] + s6 * u[17] + s7 * u[20] + s8 * u[23];
        }
    } else if (n >= 3) {
        const float s9  = SH_C3d[0] * y * (3.0f * xx - yy);
        const float s10 = SH_C3d[1] * (x * y) * z;
        const float s11 = SH_C3d[2] * y * (4.0f * zz - xx - yy);
        const float s12 = SH_C3d[3] * z * (2.0f * zz - 3.0f * xx - 3.0f * yy);
        const float s13 = SH_C3d[4] * x * (4.0f * zz - xx - yy);
        const float s14 = SH_C3d[5] * z * (xx - yy);
        const float s15 = SH_C3d[6] * x * (xx - 3.0f * yy);
        // u[k] == element 24+k : j=9 -> 0..2, j=10 -> 3..5, ... j=15 -> 18..20
        r = s9 * u[0] + s10 * u[3] + s11 * u[6]  + s12 * u[9]
          + s13 * u[12] + s14 * u[15] + s15 * u[18];
        g = s9 * u[1] + s10 * u[4] + s11 * u[7]  + s12 * u[10]
          + s13 * u[13] + s14 * u[16] + s15 * u[19];
        b = s9 * u[2] + s10 * u[5] + s11 * u[8]  + s12 * u[11]
          + s13 * u[14] + s14 * u[17] + s15 * u[20];
    }

    // pairwise reduce across the gang
    r += __shfl_xor_sync(0xffffffffu, r, 1);
    g += __shfl_xor_sync(0xffffffffu, g, 1);
    b += __shfl_xor_sync(0xffffffffu, b, 1);

    if (q == 0) {
        out_rgb[3ll * p + 0] = fmaxf(r + 0.5f, 0.0f);
        out_rgb[3ll * p + 1] = fmaxf(g + 0.5f, 0.0f);
        out_rgb[3ll * p + 2] = fmaxf(b + 0.5f, 0.0f);
        out_opac[p] = op;
    }
}

extern "C" void kernel_launch(void* const* d_in, const int* in_sizes, int n_in,
                              void* d_out, int out_size)
{
    const float* means = (const float*)d_in[0];
    const float* fdc   = (const float*)d_in[1];
    const float* frest = (const float*)d_in[2];
    const float* opac  = (const float*)d_in[3];
    const float* c2w   = (const float*)d_in[4];
    const int*   mask  = (const int*)d_in[5];
    const int*   step  = (const int*)d_in[6];

    int M = in_sizes[5];
    float* out_rgb  = (float*)d_out;
    float* out_opac = (float*)d_out + 3ll * M;

    long long threads_total = 2ll * M;
    int threads = 256;
    int blocks = (int)((threads_total + threads - 1) / threads);
    gsh_kernel<<<blocks, threads>>>(means, fdc, frest, opac, c2w, mask, step,
                                    out_rgb, out_opac, M);
}

// round 16
// speedup vs baseline: 2.6469x; 1.2165x over previous
#include <cuda_runtime.h>
#include <cuda_bf16.h>

#define SH_C0 0.28209479177387814f
#define SH_C1 0.4886025119029199f

__device__ __constant__ float SH_C2d[5] = {1.0925484305920792f, -1.0925484305920792f, 0.31539156525252005f, -1.0925484305920792f, 0.5462742152960396f};
__device__ __constant__ float SH_C3d[7] = {-0.5900435899266435f, 2.890611442640554f, -0.4570457994644658f, 0.3731763325901154f, -0.4570457994644658f, 1.445305721320277f, -0.5900435899266435f};

// Gang-of-4: four adjacent lanes per point.
// Lane q loads aligned float4s (albase + 48q .. +64) — after the s-word
// realign shift lane q owns row elements 12q..12q+11, which map to whole SH
// coefficients: lane0 j=1..4, lane1 j=5..8, lane2 j=9..12, lane3 j=13..15.
// 16-word window/lane -> ~48 regs -> ~1.5x occupancy over gang-of-2, MLP
// still structurally forced (shift consumes the window). Butterfly shfl
// reduction, lane0 writes.
// Bounds: lane3 window ends at albase+192 = row_end + 12 - 4s; last row
// (idx = N-1 ≡ 3 mod 4) has s=3 -> ends exactly at the array end. Safe.
__global__ void __launch_bounds__(256)
gsh_kernel(const float* __restrict__ means,
           const float* __restrict__ fdc,
           const float* __restrict__ frest,
           const float* __restrict__ opac,
           const float* __restrict__ c2w,
           const int*   __restrict__ mask,
           const int*   __restrict__ step,
           float* __restrict__ out_rgb,
           float* __restrict__ out_opac,
           int M)
{
    const int t = blockIdx.x * blockDim.x + threadIdx.x;
    const int p = t >> 2;            // point index
    const int q = t & 3;             // quarter
    if (p >= M) return;

    const long long idx = (long long)__ldg(mask + p);

    const long long base_bytes = 180ll * idx;
    const long long albase     = base_bytes & ~15ll;
    const int s = (int)((base_bytes - albase) >> 2);   // == idx & 3

    const float4* __restrict__ vp =
        (const float4*)((const char*)frest + albase + 48 * q);

    float4 v0 = __ldg(vp + 0);
    float4 v1 = __ldg(vp + 1);
    float4 v2 = __ldg(vp + 2);
    float4 v3 = make_float4(0.f, 0.f, 0.f, 0.f);
    if (q < 3) v3 = __ldg(vp + 3);   // lane3 needs only 12 words

    // every lane loads means (same address within gang -> coalesced);
    // lane0 additionally loads dc + opacity
    const float mx = __ldg(means + 3ll * idx + 0);
    const float my = __ldg(means + 3ll * idx + 1);
    const float mz = __ldg(means + 3ll * idx + 2);
    float d0 = 0.f, d1 = 0.f, d2 = 0.f, op = 0.f;
    if (q == 0) {
        d0 = __ldg(fdc + 3ll * idx + 0);
        d1 = __ldg(fdc + 3ll * idx + 1);
        d2 = __ldg(fdc + 3ll * idx + 2);
        op = __ldg(opac + idx);
    }

    const float camx = __ldg(c2w + 3);
    const float camy = __ldg(c2w + 7);
    const float camz = __ldg(c2w + 11);
    const int n = min(__ldg(step) / 1000, 3);

    // unpack 16-word lane window
    float u[16];
    u[0]=v0.x;  u[1]=v0.y;  u[2]=v0.z;  u[3]=v0.w;
    u[4]=v1.x;  u[5]=v1.y;  u[6]=v1.z;  u[7]=v1.w;
    u[8]=v2.x;  u[9]=v2.y;  u[10]=v2.z; u[11]=v2.w;
    u[12]=v3.x; u[13]=v3.y; u[14]=v3.z; u[15]=v3.w;

    // realign by s words: afterwards u[k] == row element (12q + k), k<=11
    if (s & 2) {
#pragma unroll
        for (int k = 0; k < 14; ++k) u[k] = u[k + 2];
    }
    if (s & 1) {
#pragma unroll
        for (int k = 0; k < 13; ++k) u[k] = u[k + 1];
    }

    // direction
    const float dx = mx - camx;
    const float dy = my - camy;
    const float dz = mz - camz;
    const float inv = rsqrtf(dx * dx + dy * dy + dz * dz);
    const float x = dx * inv, y = dy * inv, z = dz * inv;
    const float xx = x * x, yy = y * y, zz = z * z;

    float r = 0.f, g = 0.f, b = 0.f;

    if (q == 0) {
        // j=0 (dc), j=1..3 (deg1), j=4 (first deg2 coeff) -> elements 0..11
        r = SH_C0 * d0;
        g = SH_C0 * d1;
        b = SH_C0 * d2;
        if (n >= 1) {
            const float s1 = -SH_C1 * y;
            const float s2 =  SH_C1 * z;
            const float s3 = -SH_C1 * x;
            r += s1 * u[0] + s2 * u[3] + s3 * u[6];
            g += s1 * u[1] + s2 * u[4] + s3 * u[7];
            b += s1 * u[2] + s2 * u[5] + s3 * u[8];
        }
        if (n >= 2) {
            const float s4 = SH_C2d[0] * (x * y);
            r += s4 * u[9];
            g += s4 * u[10];
            b += s4 * u[11];
        }
    } else if (q == 1) {
        // j=5..8 (deg2) -> elements 12..23
        if (n >= 2) {
            const float s5 = SH_C2d[1] * (y * z);
            const float s6 = SH_C2d[2] * (2.0f * zz - xx - yy);
            const float s7 = SH_C2d[3] * (x * z);
            const float s8 = SH_C2d[4] * (xx - yy);
            r = s5 * u[0] + s6 * u[3] + s7 * u[6] + s8 * u[9];
            g = s5 * u[1] + s6 * u[4] + s7 * u[7] + s8 * u[10];
            b = s5 * u[2] + s6 * u[5] + s7 * u[8] + s8 * u[11];
        }
    } else if (q == 2) {
        // j=9..12 (deg3) -> elements 24..35
        if (n >= 3) {
            const float s9  = SH_C3d[0] * y * (3.0f * xx - yy);
            const float s10 = SH_C3d[1] * (x * y) * z;
            const float s11 = SH_C3d[2] * y * (4.0f * zz - xx - yy);
            const float s12 = SH_C3d[3] * z * (2.0f * zz - 3.0f * xx - 3.0f * yy);
            r = s9 * u[0] + s10 * u[3] + s11 * u[6] + s12 * u[9];
            g = s9 * u[1] + s10 * u[4] + s11 * u[7] + s12 * u[10];
            b = s9 * u[2] + s10 * u[5] + s11 * u[8] + s12 * u[11];
        }
    } else {
        // j=13..15 (deg3) -> elements 36..44
        if (n >= 3) {
            const float s13 = SH_C3d[4] * x * (4.0f * zz - xx - yy);
            const float s14 = SH_C3d[5] * z * (xx - yy);
            const float s15 = SH_C3d[6] * x * (xx - 3.0f * yy);
            r = s13 * u[0] + s14 * u[3] + s15 * u[6];
            g = s13 * u[1] + s14 * u[4] + s15 * u[7];
            b = s13 * u[2] + s14 * u[5] + s15 * u[8];
        }
    }

    // butterfly reduce across the gang of 4
    r += __shfl_xor_sync(0xffffffffu, r, 1);
    g += __shfl_xor_sync(0xffffffffu, g, 1);
    b += __shfl_xor_sync(0xffffffffu, b, 1);
    r += __shfl_xor_sync(0xffffffffu, r, 2);
    g += __shfl_xor_sync(0xffffffffu, g, 2);
    b += __shfl_xor_sync(0xffffffffu, b, 2);

    if (q == 0) {
        out_rgb[3ll * p + 0] = fmaxf(r + 0.5f, 0.0f);
        out_rgb[3ll * p + 1] = fmaxf(g + 0.5f, 0.0f);
        out_rgb[3ll * p + 2] = fmaxf(b + 0.5f, 0.0f);
        out_opac[p] = op;
    }
}

extern "C" void kernel_launch(void* const* d_in, const int* in_sizes, int n_in,
                              void* d_out, int out_size)
{
    const float* means = (const float*)d_in[0];
    const float* fdc   = (const float*)d_in[1];
    const float* frest = (const float*)d_in[2];
    const float* opac  = (const float*)d_in[3];
    const float* c2w   = (const float*)d_in[4];
    const int*   mask  = (const int*)d_in[5];
    const int*   step  = (const int*)d_in[6];

    int M = in_sizes[5];
    float* out_rgb  = (float*)d_out;
    float* out_opac = (float*)d_out + 3ll * M;

    long long threads_total = 4ll * M;
    int threads = 256;
    int blocks = (int)((threads_total + threads - 1) / threads);
    gsh_kernel<<<blocks, threads>>>(means, fdc, frest, opac, c2w, mask, step,
                                    out_rgb, out_opac, M);
}